// round 7
// baseline (speedup 1.0000x reference)
#include <cuda_runtime.h>

// ---------------- problem constants ----------------
#define BATCH  16
#define NHW    37
#define NPIX   1369            // 37*37
#define CIN    768
#define HIDC   256
#define NCH2   1764            // 9*14*14
#define MTOT   (BATCH*NPIX)    // 21904
#define IMG    518
#define IMGPIX (IMG*IMG)       // 268324
#define PUP    14

// ---------------- GEMM tiling ----------------
#define BM 128
#define BN 64
#define BK 16

// ---------------- device scratch (static; no allocations allowed) ----------------
__device__ float g_Wt1[9*CIN*HIDC];          // fh_w1 -> [tap][c][n]
__device__ float g_Wt2[9*CIN*HIDC];          // wp_w1 -> [tap][c][n]
__device__ float g_Wt3[HIDC*NCH2];           // wp_w2 -> [c][n]
__device__ float g_hid_fh[MTOT*HIDC];        // relu(conv1) flow head, NHWC
__device__ float g_hid_wp[MTOT*HIDC];        // relu(conv1) weight head, NHWC
__device__ float g_flow[MTOT*3];             // flow (3 ch per coarse pixel)
__device__ float g_wraw[(size_t)MTOT*NCH2];  // 1x1 conv output, [m][1764]

// ---------------- weight transposes ----------------
__global__ void k_tw1(const float* __restrict__ w1, const float* __restrict__ w2) {
    int idx = blockIdx.x * 256 + threadIdx.x;
    if (idx >= 9*CIN*HIDC) return;
    int n   = idx & 255;
    int c   = (idx >> 8) % CIN;
    int tap = (idx >> 8) / CIN;
    g_Wt1[idx] = w1[(n*CIN + c)*9 + tap];
    g_Wt2[idx] = w2[(n*CIN + c)*9 + tap];
}

__global__ void k_tw3(const float* __restrict__ w) {
    int idx = blockIdx.x * 256 + threadIdx.x;
    if (idx >= HIDC*NCH2) return;
    int n = idx % NCH2;
    int c = idx / NCH2;
    g_Wt3[idx] = w[n*HIDC + c];
}

// ---------------- fused dual 3x3 conv: both heads share the A (im2col) tiles ----
// X: tokens NHWC [MTOT][768]; W: g_Wt1/g_Wt2 [tap][c][n]
// Y1 = relu(X*W1+b1) -> g_hid_fh ; Y2 = relu(X*W2+b2) -> g_hid_wp
__global__ __launch_bounds__(256)
void k_conv3x3_fused(const float* __restrict__ X,
                     const float* __restrict__ bias1,
                     const float* __restrict__ bias2) {
    __shared__ float As [BK][BM+4];
    __shared__ float Bs1[BK][BN];
    __shared__ float Bs2[BK][BN];
    __shared__ int   nbase[BM];
    __shared__ int   s_pb[BM];
    __shared__ int   s_h[BM];
    __shared__ int   s_w[BM];

    int m0 = blockIdx.x * BM;
    int n0 = blockIdx.y * BN;
    int tid = threadIdx.x;
    int tx = tid & 15, ty = tid >> 4;

    float acc1[8][4], acc2[8][4];
#pragma unroll
    for (int i = 0; i < 8; i++)
#pragma unroll
        for (int j = 0; j < 4; j++) { acc1[i][j] = 0.f; acc2[i][j] = 0.f; }

    if (tid < BM) {
        int m = m0 + tid;
        if (m < MTOT) {
            int b = m / NPIX, pix = m % NPIX;
            s_pb[tid] = b * NPIX;
            s_h[tid]  = pix / NHW;
            s_w[tid]  = pix % NHW;
        } else {
            s_pb[tid] = -1;
        }
    }
    __syncthreads();

    for (int tap = 0; tap < 9; ++tap) {
        if (tid < BM) {
            int base = -1;
            if (s_pb[tid] >= 0) {
                int hh = s_h[tid] + tap/3 - 1;
                int ww = s_w[tid] + tap%3 - 1;
                if ((unsigned)hh < NHW && (unsigned)ww < NHW)
                    base = (s_pb[tid] + hh*NHW + ww) * CIN;
            }
            nbase[tid] = base;
        }
        const float* W1tap = g_Wt1 + tap * (CIN*HIDC);
        const float* W2tap = g_Wt2 + tap * (CIN*HIDC);
        __syncthreads();

        for (int c0 = 0; c0 < CIN; c0 += BK) {
            // A tile: 128 rows x 16 cols = 512 float4, 2 per thread
#pragma unroll
            for (int i = 0; i < 2; i++) {
                int idx = tid + i*256;
                int mm = idx >> 2;
                int kk = (idx & 3) * 4;
                int base = nbase[mm];
                float4 v = make_float4(0.f, 0.f, 0.f, 0.f);
                if (base >= 0) v = *(const float4*)(X + base + c0 + kk);
                As[kk  ][mm] = v.x;
                As[kk+1][mm] = v.y;
                As[kk+2][mm] = v.z;
                As[kk+3][mm] = v.w;
            }
            // B tiles: 16 x 64 each, 1 float4 per thread per head
            {
                int kk = tid >> 4;
                int nn = (tid & 15) * 4;
                *(float4*)&Bs1[kk][nn] = *(const float4*)(W1tap + (c0+kk)*HIDC + n0 + nn);
                *(float4*)&Bs2[kk][nn] = *(const float4*)(W2tap + (c0+kk)*HIDC + n0 + nn);
            }
            __syncthreads();
#pragma unroll
            for (int kk = 0; kk < BK; ++kk) {
                float4 a0 = *(const float4*)&As[kk][ty*8];
                float4 a1 = *(const float4*)&As[kk][ty*8+4];
                float4 b1 = *(const float4*)&Bs1[kk][tx*4];
                float4 b2 = *(const float4*)&Bs2[kk][tx*4];
                float a[8]  = {a0.x,a0.y,a0.z,a0.w,a1.x,a1.y,a1.z,a1.w};
                float w1[4] = {b1.x,b1.y,b1.z,b1.w};
                float w2[4] = {b2.x,b2.y,b2.z,b2.w};
#pragma unroll
                for (int i = 0; i < 8; i++) {
#pragma unroll
                    for (int j = 0; j < 4; j++) {
                        acc1[i][j] += a[i]*w1[j];
                        acc2[i][j] += a[i]*w2[j];
                    }
                }
            }
            __syncthreads();
        }
    }

#pragma unroll
    for (int i = 0; i < 8; i++) {
        int m = m0 + ty*8 + i;
        if (m < MTOT) {
#pragma unroll
            for (int j = 0; j < 4; j++) {
                int n = n0 + tx*4 + j;
                g_hid_fh[m*HIDC + n] = fmaxf(acc1[i][j] + bias1[n], 0.f);
                g_hid_wp[m*HIDC + n] = fmaxf(acc2[i][j] + bias2[n], 0.f);
            }
        }
    }
}

// ---------------- 1x1 conv: wraw = hid_wp @ Wt3 + b  (M=21904,N=1764,K=256) ----------------
__global__ __launch_bounds__(256)
void k_gemm2(const float* __restrict__ bias) {
    const float* A  = g_hid_wp;
    const float* Bm = g_Wt3;

    __shared__ float As[BK][BM+4];
    __shared__ float Bs[BK][BN];

    int m0 = blockIdx.x * BM;
    int n0 = blockIdx.y * BN;
    int tid = threadIdx.x;
    int tx = tid & 15, ty = tid >> 4;

    float acc[8][4];
#pragma unroll
    for (int i = 0; i < 8; i++)
#pragma unroll
        for (int j = 0; j < 4; j++) acc[i][j] = 0.f;

    for (int k0 = 0; k0 < HIDC; k0 += BK) {
#pragma unroll
        for (int i = 0; i < 2; i++) {
            int idx = tid + i*256;
            int mm = idx >> 2;
            int kk = (idx & 3) * 4;
            int m = m0 + mm;
            float4 v = make_float4(0.f, 0.f, 0.f, 0.f);
            if (m < MTOT) v = *(const float4*)(A + m*HIDC + k0 + kk);
            As[kk  ][mm] = v.x;
            As[kk+1][mm] = v.y;
            As[kk+2][mm] = v.z;
            As[kk+3][mm] = v.w;
        }
        {
            int kk = tid >> 4;
            int nn = (tid & 15) * 4;
            int n = n0 + nn;
            float4 v = make_float4(0.f, 0.f, 0.f, 0.f);
            if (n < NCH2) v = *(const float4*)(Bm + (k0+kk)*NCH2 + n);
            *(float4*)&Bs[kk][nn] = v;
        }
        __syncthreads();
#pragma unroll
        for (int kk = 0; kk < BK; ++kk) {
            float4 a0 = *(const float4*)&As[kk][ty*8];
            float4 a1 = *(const float4*)&As[kk][ty*8+4];
            float4 bv = *(const float4*)&Bs[kk][tx*4];
            float a[8] = {a0.x,a0.y,a0.z,a0.w,a1.x,a1.y,a1.z,a1.w};
            float bb[4] = {bv.x,bv.y,bv.z,bv.w};
#pragma unroll
            for (int i = 0; i < 8; i++)
#pragma unroll
                for (int j = 0; j < 4; j++) acc[i][j] += a[i]*bb[j];
        }
        __syncthreads();
    }

#pragma unroll
    for (int i = 0; i < 8; i++) {
        int m = m0 + ty*8 + i;
        if (m < MTOT) {
#pragma unroll
            for (int j = 0; j < 4; j++) {
                int n = n0 + tx*4 + j;
                if (n < NCH2)
                    g_wraw[(size_t)m*NCH2 + n] = acc[i][j] + bias[n];
            }
        }
    }
}

// ---------------- flow conv: 3x3, 256->3, one warp per pixel ----------------
__global__ __launch_bounds__(256)
void k_flowconv(const float* __restrict__ w2, const float* __restrict__ b2) {
    __shared__ float s_w[3*HIDC*9];   // 6912 floats
    int tid = threadIdx.x;
    for (int i = tid; i < 3*HIDC*9; i += 256) s_w[i] = w2[i];
    __syncthreads();

    int warp = tid >> 5, lane = tid & 31;
    int m = blockIdx.x * 8 + warp;
    if (m >= MTOT) return;
    int b = m / NPIX, pix = m % NPIX;
    int h = pix / NHW, w = pix % NHW;

    float a0 = 0.f, a1 = 0.f, a2 = 0.f;
    for (int tap = 0; tap < 9; ++tap) {
        int hh = h + tap/3 - 1, ww = w + tap%3 - 1;
        if ((unsigned)hh >= NHW || (unsigned)ww >= NHW) continue;
        const float* hrow = g_hid_fh + (b*NPIX + hh*NHW + ww) * HIDC;
#pragma unroll
        for (int j = 0; j < 8; ++j) {
            int c = lane + j*32;
            float hv = hrow[c];
            a0 += hv * s_w[(0*HIDC + c)*9 + tap];
            a1 += hv * s_w[(1*HIDC + c)*9 + tap];
            a2 += hv * s_w[(2*HIDC + c)*9 + tap];
        }
    }
#pragma unroll
    for (int off = 16; off; off >>= 1) {
        a0 += __shfl_down_sync(0xffffffffu, a0, off);
        a1 += __shfl_down_sync(0xffffffffu, a1, off);
        a2 += __shfl_down_sync(0xffffffffu, a2, off);
    }
    if (lane == 0) {
        g_flow[m*3 + 0] = a0 + b2[0];
        g_flow[m*3 + 1] = a1 + b2[1];
        g_flow[m*3 + 2] = a2 + b2[2];
    }
}

// ---------------- fused softmax + neighbor einsum + upsample + sigmoid ----------------
__global__ __launch_bounds__(256)
void k_upsample(float* __restrict__ out) {
    __shared__ float s_w[NCH2];
    __shared__ float s_nbr[9][3];

    int m = blockIdx.x;
    int b = m / NPIX, pix = m % NPIX;
    int h = pix / NHW, w = pix % NHW;
    int tid = threadIdx.x;

    const float* wrow = g_wraw + (size_t)m*NCH2;
    for (int i = tid; i < NCH2; i += 256) s_w[i] = wrow[i];

    if (tid < 27) {
        int k = tid / 3, c = tid % 3;
        int hh = h + k/3 - 1, ww = w + k%3 - 1;
        float v = 0.f;
        if ((unsigned)hh < NHW && (unsigned)ww < NHW)
            v = (float)PUP * g_flow[(b*NPIX + hh*NHW + ww)*3 + c];
        s_nbr[k][c] = v;
    }
    __syncthreads();

    if (tid < PUP*PUP) {
        int p = tid / PUP, q = tid % PUP;
        float wv[9], mx = -1e30f;
#pragma unroll
        for (int k = 0; k < 9; ++k) { wv[k] = s_w[k*196 + tid]; mx = fmaxf(mx, wv[k]); }
        float s = 0.f;
#pragma unroll
        for (int k = 0; k < 9; ++k) { wv[k] = expf(wv[k] - mx); s += wv[k]; }
        float inv = 1.0f / s;
        float u0 = 0.f, u1 = 0.f, u2 = 0.f;
#pragma unroll
        for (int k = 0; k < 9; ++k) {
            float wk = wv[k] * inv;
            u0 += wk * s_nbr[k][0];
            u1 += wk * s_nbr[k][1];
            u2 += wk * s_nbr[k][2];
        }
        int Hy = h*PUP + p, Wx = w*PUP + q;
        size_t po = (size_t)Hy*IMG + Wx;
        out[(size_t)(b*2 + 0)*IMGPIX + po] = u0;
        out[(size_t)(b*2 + 1)*IMGPIX + po] = u1;
        out[(size_t)(2*BATCH)*IMGPIX + (size_t)b*IMGPIX + po] = 1.0f / (1.0f + expf(-u2));
    }
}

// ---------------- launch ----------------
extern "C" void kernel_launch(void* const* d_in, const int* in_sizes, int n_in,
                              void* d_out, int out_size) {
    const float* tokens = (const float*)d_in[0];
    const float* fh_w1  = (const float*)d_in[1];
    const float* fh_b1  = (const float*)d_in[2];
    const float* fh_w2  = (const float*)d_in[3];
    const float* fh_b2  = (const float*)d_in[4];
    const float* wp_w1  = (const float*)d_in[5];
    const float* wp_b1  = (const float*)d_in[6];
    const float* wp_w2  = (const float*)d_in[7];
    const float* wp_b2  = (const float*)d_in[8];
    float* out = (float*)d_out;

    // weight layout transforms
    k_tw1<<<(9*CIN*HIDC + 255)/256, 256>>>(fh_w1, wp_w1);
    k_tw3<<<(HIDC*NCH2 + 255)/256, 256>>>(wp_w2);

    dim3 g1((MTOT + BM - 1)/BM, HIDC/BN);          // 172 x 4
    k_conv3x3_fused<<<g1, 256>>>(tokens, fh_b1, wp_b1);

    dim3 g2((MTOT + BM - 1)/BM, (NCH2 + BN - 1)/BN); // 172 x 28
    k_gemm2<<<g2, 256>>>(wp_b2);

    k_flowconv<<<(MTOT + 7)/8, 256>>>(fh_w2, fh_b2);

    k_upsample<<<MTOT, 256>>>(out);
}

// round 16
// speedup vs baseline: 1.6947x; 1.6947x over previous
#include <cuda_runtime.h>
#include <cuda_bf16.h>
#include <cstdint>

// ---------------- problem constants ----------------
#define BATCH  16
#define NHW    37
#define NPIX   1369
#define CIN    768
#define HIDC   256
#define NCH2   1764
#define MTOT   (BATCH*NPIX)    // 21904
#define IMG    518
#define IMGPIX (IMG*IMG)
#define PUP    14

// ---------------- SIMT GEMM tiling (gemm2) ----------------
#define BM 128
#define BN 64
#define BK 16

// ---------------- device scratch ----------------
__device__ __nv_bfloat16 g_thi[MTOT*CIN];            // tokens hi
__device__ __nv_bfloat16 g_tlo[MTOT*CIN];            // tokens lo (residual)
__device__ __nv_bfloat16 g_whi[2*9*HIDC*CIN];        // weights hi  [head][tap][n][c]
__device__ __nv_bfloat16 g_wlo[2*9*HIDC*CIN];        // weights lo
__device__ float g_Wt3[HIDC*NCH2];                   // wp_w2 -> [c][n]
__device__ float g_hid_fh[MTOT*HIDC];
__device__ float g_hid_wp[MTOT*HIDC];
__device__ float g_flow[MTOT*3];
__device__ float g_wraw[(size_t)MTOT*NCH2];

// ---------------- prep kernels ----------------
__global__ void k_split(const float* __restrict__ t) {
    int idx = blockIdx.x * 256 + threadIdx.x;
    if (idx >= MTOT*CIN) return;
    float x = t[idx];
    __nv_bfloat16 hi = __float2bfloat16(x);
    float r = x - __bfloat162float(hi);
    g_thi[idx] = hi;
    g_tlo[idx] = __float2bfloat16(r);
}

__global__ void k_prep_w(const float* __restrict__ w1, const float* __restrict__ w2) {
    int idx = blockIdx.x * 256 + threadIdx.x;
    if (idx >= 2*9*HIDC*CIN) return;
    int c    = idx % CIN;
    int n    = (idx / CIN) % HIDC;
    int tap  = (idx / (CIN*HIDC)) % 9;
    int head = idx / (CIN*HIDC*9);
    const float* src = head ? w2 : w1;
    float v = src[(n*CIN + c)*9 + tap];
    __nv_bfloat16 hi = __float2bfloat16(v);
    float r = v - __bfloat162float(hi);
    g_whi[idx] = hi;
    g_wlo[idx] = __float2bfloat16(r);
}

__global__ void k_tw3(const float* __restrict__ w) {
    int idx = blockIdx.x * 256 + threadIdx.x;
    if (idx >= HIDC*NCH2) return;
    int n = idx % NCH2;
    int c = idx / NCH2;
    g_Wt3[idx] = w[n*HIDC + c];
}

// ---------------- mma.sync m16n8k16 bf16 (baseline PTX, OK on compute_103) ----------------
__device__ __forceinline__ void mma16816(float* c, const uint32_t* a, const uint32_t* b) {
    asm volatile(
        "mma.sync.aligned.m16n8k16.row.col.f32.bf16.bf16.f32 "
        "{%0,%1,%2,%3}, {%4,%5,%6,%7}, {%8,%9}, {%0,%1,%2,%3};"
        : "+f"(c[0]), "+f"(c[1]), "+f"(c[2]), "+f"(c[3])
        : "r"(a[0]), "r"(a[1]), "r"(a[2]), "r"(a[3]), "r"(b[0]), "r"(b[1]));
}

// ---------------- conv via tensor-core mma: 9 shifted GEMMs, bf16-split ----------------
// grid (172, 8): x = m-block of 128 rows; y: head = y>>2, n0 = (y&3)*64
// block 256 threads = 8 warps (4m x 2n); warp tile 32m x 32n (2x4 m16n8 tiles)
#define CBK   32
#define CPAD  40   // smem row stride in elems
__global__ __launch_bounds__(256)
void k_conv_mma(const float* __restrict__ bias1, const float* __restrict__ bias2) {
    __shared__ __align__(16) __nv_bfloat16 Ah[128][CPAD];
    __shared__ __align__(16) __nv_bfloat16 Al[128][CPAD];
    __shared__ __align__(16) __nv_bfloat16 Bh[64][CPAD];
    __shared__ __align__(16) __nv_bfloat16 Bl[64][CPAD];
    __shared__ int nbase[128];

    int tid = threadIdx.x;
    int wid = tid >> 5, lane = tid & 31;
    int g = lane >> 2, tig = lane & 3;
    int wm = wid >> 1, wn = wid & 1;     // 4 x 2 warp grid
    int head = blockIdx.y >> 2;
    int n0   = (blockIdx.y & 3) * 64;
    int m0   = blockIdx.x * 128;

    // this thread's row coords (for nbase of row tid<128)
    int myb = -1, myh = 0, myw = 0;
    if (tid < 128) {
        int m = m0 + tid;
        if (m < MTOT) { myb = m / NPIX; int px = m % NPIX; myh = px / NHW; myw = px % NHW; }
    }

    const __nv_bfloat16* wh = g_whi + (size_t)(head*9) * HIDC * CIN;
    const __nv_bfloat16* wl = g_wlo + (size_t)(head*9) * HIDC * CIN;

    float acc[2][4][4];
#pragma unroll
    for (int i = 0; i < 2; i++)
#pragma unroll
        for (int j = 0; j < 4; j++)
#pragma unroll
            for (int k = 0; k < 4; k++) acc[i][j][k] = 0.f;

    for (int tap = 0; tap < 9; ++tap) {
        __syncthreads();   // protect nbase rewrite vs prior chunk's reads
        if (tid < 128) {
            int nb = -1;
            if (myb >= 0) {
                int hh = myh + tap/3 - 1, ww = myw + tap%3 - 1;
                if ((unsigned)hh < NHW && (unsigned)ww < NHW)
                    nb = (myb*NPIX + hh*NHW + ww) * CIN;
            }
            nbase[tid] = nb;
        }
        __syncthreads();

        for (int c0 = 0; c0 < CIN; c0 += CBK) {
            // stage A: 2(hi/lo) x 128 rows x 4 segs (8 elems = 16B) = 1024 units
#pragma unroll
            for (int i = 0; i < 4; i++) {
                int u = tid + i*256;
                int seg  = u & 3;
                int row  = (u >> 2) & 127;
                int hilo = (u >> 9) & 1;
                int nb = nbase[row];
                uint4 v = make_uint4(0,0,0,0);
                if (nb >= 0)
                    v = *(const uint4*)((hilo ? g_tlo : g_thi) + nb + c0 + seg*8);
                __nv_bfloat16* dst = (hilo ? &Al[0][0] : &Ah[0][0]);
                *(uint4*)(dst + row*CPAD + seg*8) = v;
            }
            // stage B: 2(hi/lo) x 64 rows x 4 segs = 512 units
#pragma unroll
            for (int i = 0; i < 2; i++) {
                int u = tid + i*256;
                int seg  = u & 3;
                int row  = (u >> 2) & 63;
                int hilo = (u >> 8) & 1;
                const __nv_bfloat16* src = (hilo ? wl : wh) +
                    ((size_t)tap*HIDC + n0 + row)*CIN + c0 + seg*8;
                uint4 v = *(const uint4*)src;
                __nv_bfloat16* dst = (hilo ? &Bl[0][0] : &Bh[0][0]);
                *(uint4*)(dst + row*CPAD + seg*8) = v;
            }
            __syncthreads();

#pragma unroll
            for (int kk = 0; kk < CBK/16; ++kk) {
                int cb = kk*16 + tig*2;
                uint32_t ah[2][4], al[2][4], bh[4][2], bl[4][2];
#pragma unroll
                for (int i = 0; i < 2; i++) {
                    int r0 = wm*32 + i*16 + g;
                    ah[i][0] = *(const uint32_t*)&Ah[r0  ][cb  ];
                    ah[i][1] = *(const uint32_t*)&Ah[r0+8][cb  ];
                    ah[i][2] = *(const uint32_t*)&Ah[r0  ][cb+8];
                    ah[i][3] = *(const uint32_t*)&Ah[r0+8][cb+8];
                    al[i][0] = *(const uint32_t*)&Al[r0  ][cb  ];
                    al[i][1] = *(const uint32_t*)&Al[r0+8][cb  ];
                    al[i][2] = *(const uint32_t*)&Al[r0  ][cb+8];
                    al[i][3] = *(const uint32_t*)&Al[r0+8][cb+8];
                }
#pragma unroll
                for (int j = 0; j < 4; j++) {
                    int n = wn*32 + j*8 + g;
                    bh[j][0] = *(const uint32_t*)&Bh[n][cb  ];
                    bh[j][1] = *(const uint32_t*)&Bh[n][cb+8];
                    bl[j][0] = *(const uint32_t*)&Bl[n][cb  ];
                    bl[j][1] = *(const uint32_t*)&Bl[n][cb+8];
                }
#pragma unroll
                for (int i = 0; i < 2; i++)
#pragma unroll
                    for (int j = 0; j < 4; j++) {
                        mma16816(acc[i][j], ah[i], bh[j]);
                        mma16816(acc[i][j], ah[i], bl[j]);
                        mma16816(acc[i][j], al[i], bh[j]);
                    }
            }
            __syncthreads();
        }
    }

    // epilogue: bias + relu
    const float* bias = head ? bias2 : bias1;
    float* dst = head ? g_hid_wp : g_hid_fh;
#pragma unroll
    for (int i = 0; i < 2; i++) {
#pragma unroll
        for (int j = 0; j < 4; j++) {
            int col = n0 + wn*32 + j*8 + tig*2;
            float b0 = bias[col], b1 = bias[col+1];
            int mA = m0 + wm*32 + i*16 + g;
            int mB = mA + 8;
            if (mA < MTOT) {
                float2 o;
                o.x = fmaxf(acc[i][j][0] + b0, 0.f);
                o.y = fmaxf(acc[i][j][1] + b1, 0.f);
                *(float2*)(dst + (size_t)mA*HIDC + col) = o;
            }
            if (mB < MTOT) {
                float2 o;
                o.x = fmaxf(acc[i][j][2] + b0, 0.f);
                o.y = fmaxf(acc[i][j][3] + b1, 0.f);
                *(float2*)(dst + (size_t)mB*HIDC + col) = o;
            }
        }
    }
}

// ---------------- 1x1 conv: wraw = hid_wp @ Wt3 + b  (M=21904,N=1764,K=256) ----------------
__global__ __launch_bounds__(256)
void k_gemm2(const float* __restrict__ bias) {
    const float* A  = g_hid_wp;
    const float* Bm = g_Wt3;

    __shared__ float As[BK][BM+4];
    __shared__ float Bs[BK][BN];

    int m0 = blockIdx.x * BM;
    int n0 = blockIdx.y * BN;
    int tid = threadIdx.x;
    int tx = tid & 15, ty = tid >> 4;

    float acc[8][4];
#pragma unroll
    for (int i = 0; i < 8; i++)
#pragma unroll
        for (int j = 0; j < 4; j++) acc[i][j] = 0.f;

    for (int k0 = 0; k0 < HIDC; k0 += BK) {
#pragma unroll
        for (int i = 0; i < 2; i++) {
            int idx = tid + i*256;
            int mm = idx >> 2;
            int kk = (idx & 3) * 4;
            int m = m0 + mm;
            float4 v = make_float4(0.f, 0.f, 0.f, 0.f);
            if (m < MTOT) v = *(const float4*)(A + m*HIDC + k0 + kk);
            As[kk  ][mm] = v.x;
            As[kk+1][mm] = v.y;
            As[kk+2][mm] = v.z;
            As[kk+3][mm] = v.w;
        }
        {
            int kk = tid >> 4;
            int nn = (tid & 15) * 4;
            int n = n0 + nn;
            float4 v = make_float4(0.f, 0.f, 0.f, 0.f);
            if (n < NCH2) v = *(const float4*)(Bm + (k0+kk)*NCH2 + n);
            *(float4*)&Bs[kk][nn] = v;
        }
        __syncthreads();
#pragma unroll
        for (int kk = 0; kk < BK; ++kk) {
            float4 a0 = *(const float4*)&As[kk][ty*8];
            float4 a1 = *(const float4*)&As[kk][ty*8+4];
            float4 bv = *(const float4*)&Bs[kk][tx*4];
            float a[8] = {a0.x,a0.y,a0.z,a0.w,a1.x,a1.y,a1.z,a1.w};
            float bb[4] = {bv.x,bv.y,bv.z,bv.w};
#pragma unroll
            for (int i = 0; i < 8; i++)
#pragma unroll
                for (int j = 0; j < 4; j++) acc[i][j] += a[i]*bb[j];
        }
        __syncthreads();
    }

#pragma unroll
    for (int i = 0; i < 8; i++) {
        int m = m0 + ty*8 + i;
        if (m < MTOT) {
#pragma unroll
            for (int j = 0; j < 4; j++) {
                int n = n0 + tx*4 + j;
                if (n < NCH2)
                    g_wraw[(size_t)m*NCH2 + n] = acc[i][j] + bias[n];
            }
        }
    }
}

// ---------------- flow conv: 3x3, 256->3, one warp per pixel ----------------
__global__ __launch_bounds__(256)
void k_flowconv(const float* __restrict__ w2, const float* __restrict__ b2) {
    __shared__ float s_w[3*HIDC*9];
    int tid = threadIdx.x;
    for (int i = tid; i < 3*HIDC*9; i += 256) s_w[i] = w2[i];
    __syncthreads();

    int warp = tid >> 5, lane = tid & 31;
    int m = blockIdx.x * 8 + warp;
    if (m >= MTOT) return;
    int b = m / NPIX, pix = m % NPIX;
    int h = pix / NHW, w = pix % NHW;

    float a0 = 0.f, a1 = 0.f, a2 = 0.f;
    for (int tap = 0; tap < 9; ++tap) {
        int hh = h + tap/3 - 1, ww = w + tap%3 - 1;
        if ((unsigned)hh >= NHW || (unsigned)ww >= NHW) continue;
        const float* hrow = g_hid_fh + (b*NPIX + hh*NHW + ww) * HIDC;
#pragma unroll
        for (int j = 0; j < 8; ++j) {
            int c = lane + j*32;
            float hv = hrow[c];
            a0 += hv * s_w[(0*HIDC + c)*9 + tap];
            a1 += hv * s_w[(1*HIDC + c)*9 + tap];
            a2 += hv * s_w[(2*HIDC + c)*9 + tap];
        }
    }
#pragma unroll
    for (int off = 16; off; off >>= 1) {
        a0 += __shfl_down_sync(0xffffffffu, a0, off);
        a1 += __shfl_down_sync(0xffffffffu, a1, off);
        a2 += __shfl_down_sync(0xffffffffu, a2, off);
    }
    if (lane == 0) {
        g_flow[m*3 + 0] = a0 + b2[0];
        g_flow[m*3 + 1] = a1 + b2[1];
        g_flow[m*3 + 2] = a2 + b2[2];
    }
}

// ---------------- fused softmax + neighbor einsum + upsample + sigmoid ----------------
__global__ __launch_bounds__(256)
void k_upsample(float* __restrict__ out) {
    __shared__ float s_w[NCH2];
    __shared__ float s_nbr[9][3];

    int m = blockIdx.x;
    int b = m / NPIX, pix = m % NPIX;
    int h = pix / NHW, w = pix % NHW;
    int tid = threadIdx.x;

    const float* wrow = g_wraw + (size_t)m*NCH2;
    for (int i = tid; i < NCH2; i += 256) s_w[i] = wrow[i];

    if (tid < 27) {
        int k = tid / 3, c = tid % 3;
        int hh = h + k/3 - 1, ww = w + k%3 - 1;
        float v = 0.f;
        if ((unsigned)hh < NHW && (unsigned)ww < NHW)
            v = (float)PUP * g_flow[(b*NPIX + hh*NHW + ww)*3 + c];
        s_nbr[k][c] = v;
    }
    __syncthreads();

    if (tid < PUP*PUP) {
        float wv[9], mx = -1e30f;
#pragma unroll
        for (int k = 0; k < 9; ++k) { wv[k] = s_w[k*196 + tid]; mx = fmaxf(mx, wv[k]); }
        float s = 0.f;
#pragma unroll
        for (int k = 0; k < 9; ++k) { wv[k] = expf(wv[k] - mx); s += wv[k]; }
        float inv = 1.0f / s;
        float u0 = 0.f, u1 = 0.f, u2 = 0.f;
#pragma unroll
        for (int k = 0; k < 9; ++k) {
            float wk = wv[k] * inv;
            u0 += wk * s_nbr[k][0];
            u1 += wk * s_nbr[k][1];
            u2 += wk * s_nbr[k][2];
        }
        int p = tid / PUP, q = tid % PUP;
        int Hy = h*PUP + p, Wx = w*PUP + q;
        size_t po = (size_t)Hy*IMG + Wx;
        out[(size_t)(b*2 + 0)*IMGPIX + po] = u0;
        out[(size_t)(b*2 + 1)*IMGPIX + po] = u1;
        out[(size_t)(2*BATCH)*IMGPIX + (size_t)b*IMGPIX + po] = 1.0f / (1.0f + expf(-u2));
    }
}

// ---------------- launch ----------------
extern "C" void kernel_launch(void* const* d_in, const int* in_sizes, int n_in,
                              void* d_out, int out_size) {
    const float* tokens = (const float*)d_in[0];
    const float* fh_w1  = (const float*)d_in[1];
    const float* fh_b1  = (const float*)d_in[2];
    const float* fh_w2  = (const float*)d_in[3];
    const float* fh_b2  = (const float*)d_in[4];
    const float* wp_w1  = (const float*)d_in[5];
    const float* wp_b1  = (const float*)d_in[6];
    const float* wp_w2  = (const float*)d_in[7];
    const float* wp_b2  = (const float*)d_in[8];
    float* out = (float*)d_out;

    k_split<<<(MTOT*CIN + 255)/256, 256>>>(tokens);
    k_prep_w<<<(2*9*HIDC*CIN + 255)/256, 256>>>(fh_w1, wp_w1);
    k_tw3<<<(HIDC*NCH2 + 255)/256, 256>>>(wp_w2);

    dim3 gc((MTOT + 127)/128, 8);   // 172 x (2 heads x 4 n-quarters)
    k_conv_mma<<<gc, 256>>>(fh_b1, wp_b1);

    dim3 g2((MTOT + BM - 1)/BM, (NCH2 + BN - 1)/BN);
    k_gemm2<<<g2, 256>>>(wp_b2);

    k_flowconv<<<(MTOT + 7)/8, 256>>>(fh_w2, fh_b2);

    k_upsample<<<MTOT, 256>>>(out);
}